// round 1
// baseline (speedup 1.0000x reference)
#include <cuda_runtime.h>

#define NN 4096
#define DD 128
#define ITERS 100
#define GRID_SINK 128
#define EPSV 1e-8f

// ---------------- static device scratch (allocation-free rule) ----------------
__device__ __align__(256) float g_K[(size_t)NN * NN];   // 64 MB
__device__ __align__(256) float g_C[(size_t)NN * NN];   // 64 MB
__device__ __align__(256) float g_u[NN];
__device__ __align__(256) float g_v[NN];
__device__ __align__(256) float g_xsq[NN];
__device__ __align__(256) float g_ysq[NN];
__device__ double g_part[3 * GRID_SINK];
__device__ unsigned g_cnt = 0;
__device__ volatile unsigned g_gen = 0;

// ---------------- grid-wide barrier (single-wave persistent kernel) -----------
__device__ __forceinline__ void grid_barrier() {
    __syncthreads();
    if (threadIdx.x == 0) {
        __threadfence();                       // release: flush this CTA's stores
        unsigned gen = g_gen;
        if (atomicAdd(&g_cnt, 1u) == GRID_SINK - 1) {
            atomicExch(&g_cnt, 0u);
            __threadfence();
            g_gen = gen + 1;                   // release the others
        } else {
            while (g_gen == gen) { }           // volatile spin (L2)
        }
        __threadfence();                       // acquire: CCTL.IVALL invalidates L1
    }
    __syncthreads();
}

// ---------------- row squared norms ------------------------------------------
__global__ void rowsq_kernel(const float* __restrict__ x, const float* __restrict__ y) {
    int gw = (blockIdx.x * blockDim.x + threadIdx.x) >> 5;   // global warp id, 1 warp/row
    int lane = threadIdx.x & 31;
    const float* src;
    float* dst;
    int row;
    if (gw < NN) { src = x; dst = g_xsq; row = gw; }
    else         { src = y; dst = g_ysq; row = gw - NN; }
    float4 v = *(const float4*)(src + (size_t)row * DD + lane * 4);
    float s = v.x * v.x + v.y * v.y + v.z * v.z + v.w * v.w;
#pragma unroll
    for (int o = 16; o; o >>= 1) s += __shfl_xor_sync(0xffffffffu, s, o);
    if (lane == 0) dst[row] = s;
}

// ---------------- build C and K (tiled fp32 GEMM + exp) ----------------------
// 64x64 output tile per CTA, 256 threads, 4x4 register tile per thread.
__global__ void __launch_bounds__(256) build_kernel(const float* __restrict__ x,
                                                    const float* __restrict__ y) {
    __shared__ float sx[64][33];
    __shared__ float sy[64][33];
    const int tid = threadIdx.x;
    const int tx = tid & 15, ty = tid >> 4;
    const int row0 = blockIdx.y << 6, col0 = blockIdx.x << 6;

    float acc[4][4] = {};

    for (int kc = 0; kc < DD; kc += 32) {
        __syncthreads();
#pragma unroll
        for (int q = 0; q < 2; q++) {
            int idx = tid + (q << 8);          // 0..511 float4 slots
            int r = idx >> 3, kk = (idx & 7) << 2;
            float4 a = *(const float4*)(x + (size_t)(row0 + r) * DD + kc + kk);
            sx[r][kk] = a.x; sx[r][kk + 1] = a.y; sx[r][kk + 2] = a.z; sx[r][kk + 3] = a.w;
            float4 b = *(const float4*)(y + (size_t)(col0 + r) * DD + kc + kk);
            sy[r][kk] = b.x; sy[r][kk + 1] = b.y; sy[r][kk + 2] = b.z; sy[r][kk + 3] = b.w;
        }
        __syncthreads();
#pragma unroll
        for (int k = 0; k < 32; k++) {
            float xa[4], yb[4];
#pragma unroll
            for (int a = 0; a < 4; a++) xa[a] = sx[ty * 4 + a][k];
#pragma unroll
            for (int b = 0; b < 4; b++) yb[b] = sy[tx * 4 + b][k];
#pragma unroll
            for (int a = 0; a < 4; a++)
#pragma unroll
                for (int b = 0; b < 4; b++)
                    acc[a][b] = fmaf(xa[a], yb[b], acc[a][b]);
        }
    }

    float xs[4], ys[4];
#pragma unroll
    for (int a = 0; a < 4; a++) xs[a] = g_xsq[row0 + ty * 4 + a];
#pragma unroll
    for (int b = 0; b < 4; b++) ys[b] = g_ysq[col0 + tx * 4 + b];

#pragma unroll
    for (int a = 0; a < 4; a++) {
        size_t off = (size_t)(row0 + ty * 4 + a) * NN + col0 + tx * 4;
        float c[4], kk[4];
#pragma unroll
        for (int b = 0; b < 4; b++) {
            c[b] = fmaxf(xs[a] + ys[b] - 2.0f * acc[a][b], 0.0f);
            kk[b] = __expf(-20.0f * c[b]);     // 1/REG = 20
        }
        *(float4*)(g_C + off) = make_float4(c[0], c[1], c[2], c[3]);
        *(float4*)(g_K + off) = make_float4(kk[0], kk[1], kk[2], kk[3]);
    }
}

// ---------------- persistent Sinkhorn kernel ----------------------------------
__global__ void __launch_bounds__(256, 1) sinkhorn_kernel() {
    __shared__ float svec[NN];        // staged u or v (16 KB)
    __shared__ float red[8][32];
    const int c = blockIdx.x;
    const int tid = threadIdx.x;
    const int lane = tid & 31, w = tid >> 5;
    const float MU = 1.0f / 4096.0f;  // mu == nu == 1/n

    if (tid < 32) g_u[c * 32 + tid] = 1.0f;
    grid_barrier();

    for (int it = 0; it < ITERS; it++) {
        // ---- Phase A: t = K^T u ; v = nu / (t + eps). CTA owns 32 columns. ----
        {
            float4* s4 = (float4*)svec;
            const float4* gu4 = (const float4*)g_u;
#pragma unroll
            for (int q = 0; q < 4; q++) s4[tid + q * 256] = gu4[tid + q * 256];
            __syncthreads();

            const float* Kp = g_K + (size_t)(w * 512) * NN + c * 32 + lane;
            const float* up = svec + w * 512;
            float acc = 0.0f;
#pragma unroll 4
            for (int i8 = 0; i8 < 64; i8++) {
                float4 ua = *(const float4*)(up);
                float4 ub = *(const float4*)(up + 4);
                acc = fmaf(__ldcg(Kp),           ua.x, acc);
                acc = fmaf(__ldcg(Kp + 1 * NN),  ua.y, acc);
                acc = fmaf(__ldcg(Kp + 2 * NN),  ua.z, acc);
                acc = fmaf(__ldcg(Kp + 3 * NN),  ua.w, acc);
                acc = fmaf(__ldcg(Kp + 4 * NN),  ub.x, acc);
                acc = fmaf(__ldcg(Kp + 5 * NN),  ub.y, acc);
                acc = fmaf(__ldcg(Kp + 6 * NN),  ub.z, acc);
                acc = fmaf(__ldcg(Kp + 7 * NN),  ub.w, acc);
                Kp += 8 * NN;
                up += 8;
            }
            red[w][lane] = acc;
            __syncthreads();
            if (tid < 32) {
                float t = red[0][tid];
#pragma unroll
                for (int w2 = 1; w2 < 8; w2++) t += red[w2][tid];
                g_v[c * 32 + tid] = MU / (t + EPSV);
            }
        }
        grid_barrier();

        // ---- Phase B: s = K v ; u = mu / (s + eps). CTA owns 32 rows. --------
        {
            float4* s4 = (float4*)svec;
            const float4* gv4 = (const float4*)g_v;
#pragma unroll
            for (int q = 0; q < 4; q++) s4[tid + q * 256] = gv4[tid + q * 256];
            __syncthreads();

            const float4* sv4 = (const float4*)svec;
#pragma unroll
            for (int rr = 0; rr < 4; rr++) {
                int row = c * 32 + w * 4 + rr;
                const float4* K4 = (const float4*)(g_K + (size_t)row * NN);
                float acc = 0.0f;
#pragma unroll 8
                for (int k = 0; k < 32; k++) {
                    float4 kk = __ldcg(K4 + lane + k * 32);
                    float4 vv = sv4[lane + k * 32];
                    acc = fmaf(kk.x, vv.x, acc);
                    acc = fmaf(kk.y, vv.y, acc);
                    acc = fmaf(kk.z, vv.z, acc);
                    acc = fmaf(kk.w, vv.w, acc);
                }
#pragma unroll
                for (int o = 16; o; o >>= 1) acc += __shfl_xor_sync(0xffffffffu, acc, o);
                if (lane == 0) g_u[row] = MU / (acc + EPSV);
            }
        }
        grid_barrier();
    }
}

// ---------------- loss = sum_ij u_i K_ij C_ij v_j ------------------------------
__global__ void __launch_bounds__(256) loss_kernel(int pairIdx) {
    __shared__ float svec[NN];
    __shared__ double sred[8];
    const int c = blockIdx.x;
    const int tid = threadIdx.x;
    const int lane = tid & 31, w = tid >> 5;

    float4* s4 = (float4*)svec;
    const float4* gv4 = (const float4*)g_v;
#pragma unroll
    for (int q = 0; q < 4; q++) s4[tid + q * 256] = gv4[tid + q * 256];
    __syncthreads();

    const float4* sv4 = (const float4*)svec;
    double dacc = 0.0;
#pragma unroll
    for (int rr = 0; rr < 4; rr++) {
        int row = c * 32 + w * 4 + rr;
        const float4* K4 = (const float4*)(g_K + (size_t)row * NN);
        const float4* C4 = (const float4*)(g_C + (size_t)row * NN);
        float acc = 0.0f;
#pragma unroll 4
        for (int k = 0; k < 32; k++) {
            float4 kk = __ldcg(K4 + lane + k * 32);
            float4 cc = __ldcg(C4 + lane + k * 32);
            float4 vv = sv4[lane + k * 32];
            acc = fmaf(kk.x * cc.x, vv.x, acc);
            acc = fmaf(kk.y * cc.y, vv.y, acc);
            acc = fmaf(kk.z * cc.z, vv.z, acc);
            acc = fmaf(kk.w * cc.w, vv.w, acc);
        }
#pragma unroll
        for (int o = 16; o; o >>= 1) acc += __shfl_xor_sync(0xffffffffu, acc, o);
        if (lane == 0) dacc += (double)acc * (double)g_u[row];
    }
    if (lane == 0) sred[w] = dacc;
    __syncthreads();
    if (tid == 0) {
        double s = 0.0;
#pragma unroll
        for (int i = 0; i < 8; i++) s += sred[i];
        g_part[pairIdx * GRID_SINK + c] = s;
    }
}

// ---------------- final reduction ---------------------------------------------
__global__ void final_kernel(float* out) {
    __shared__ double sd[128];
    int t = threadIdx.x;
    double s = g_part[t] + g_part[t + 128] + g_part[t + 256];
    sd[t] = s;
    __syncthreads();
    for (int o = 64; o; o >>= 1) {
        if (t < o) sd[t] += sd[t + o];
        __syncthreads();
    }
    if (t == 0) out[0] = (float)(sd[0] / 3.0);
}

// ---------------- launch -------------------------------------------------------
extern "C" void kernel_launch(void* const* d_in, const int* in_sizes, int n_in,
                              void* d_out, int out_size) {
    const float* z[3] = {(const float*)d_in[0], (const float*)d_in[1], (const float*)d_in[2]};
    const int pa[3] = {0, 0, 1};
    const int pb[3] = {1, 2, 2};

    for (int p = 0; p < 3; p++) {
        const float* x = z[pa[p]];
        const float* y = z[pb[p]];
        rowsq_kernel<<<1024, 256>>>(x, y);
        build_kernel<<<dim3(64, 64), 256>>>(x, y);
        sinkhorn_kernel<<<GRID_SINK, 256>>>();
        loss_kernel<<<GRID_SINK, 256>>>(p);
    }
    final_kernel<<<1, 128>>>((float*)d_out);
}